// round 14
// baseline (speedup 1.0000x reference)
#include <cuda_runtime.h>
#include <cstdint>

#define RS 256
#define NV 2048
#define NF 4096
#define IMGH 480
#define IMGW 640
#define NPIX (IMGH * IMGW)
#define FBLK (NPIX / 1024)   // finalize blocks (4 px/thread)
#define THRESH (-8.5f)       // exact: dmin < -8.5 -> factor == 1.0f bitwise
#define NSUPER 64            // 8x8 super-tiles of 32x32 px
#define RT 512               // raster CTA threads
#define CHUNK 512            // faces per cull/raster round
#define NHALF 2              // face-range splits per tile
#define NTILE 512            // 16x8-px tiles: 16 x 32

__device__ float4 g_face[NF * 3];
__device__ uchar4 g_fbbox[NF];       // pixel bbox of {dmin > THRESH}: x0,x1,y0,y1
__device__ float  g_prod[NHALF * RS * RS];
__device__ unsigned long long g_loss_fx;
__device__ unsigned int g_done;
__device__ unsigned short g_superlist[NSUPER][NF];
__device__ int    g_supercount[NSUPER];

// ---------------------------------------------------------------------------
// Kernel 1: fused se3_exp + vertex transform + projection + face coefficients
// + exact expanded-triangle bbox per face.
// 4 CTAs: each redundantly transforms verts (cheap), builds NF/4 faces.
// ---------------------------------------------------------------------------
__global__ __launch_bounds__(512) void setup_face_kernel(
        const float* __restrict__ dof,
        const float* __restrict__ verts,
        const float* __restrict__ Kin,
        const int*   __restrict__ faces) {
    __shared__ float2 sxy[NV];
    __shared__ float sR[9], sT[3], sK[9];
    int tid = threadIdx.x;
    if (blockIdx.x == 0 && tid == 1) { g_loss_fx = 0ull; g_done = 0u; }
    if (tid == 0) {
        float v0 = dof[0], v1 = dof[1], v2 = dof[2];
        float w0 = dof[3], w1 = dof[4], w2 = dof[5];
        float th2 = w0 * w0 + w1 * w1 + w2 * w2;
        float th  = sqrtf(th2 + 1e-30f);
        bool small = th < 1e-4f;
        float th_s  = small ? 1.f : th;
        float th2_s = small ? 1.f : th2;
        float A = small ? (1.f - th2 / 6.f)   : (sinf(th_s) / th_s);
        float B = small ? (0.5f - th2 / 24.f) : ((1.f - cosf(th_s)) / th2_s);
        float C = small ? (1.f / 6.f - th2 / 120.f)
                        : ((th_s - sinf(th_s)) / (th2_s * th_s));
        float Kx[9] = {0.f, -w2,  w1,
                       w2,  0.f, -w0,
                      -w1,  w0,  0.f};
        float K2[9];
        #pragma unroll
        for (int r = 0; r < 3; r++)
            #pragma unroll
            for (int c = 0; c < 3; c++) {
                float acc = 0.f;
                #pragma unroll
                for (int k = 0; k < 3; k++) acc += Kx[r * 3 + k] * Kx[k * 3 + c];
                K2[r * 3 + c] = acc;
            }
        float V[9];
        #pragma unroll
        for (int i = 0; i < 9; i++) {
            float I = (i == 0 || i == 4 || i == 8) ? 1.f : 0.f;
            sR[i] = I + A * Kx[i] + B * K2[i];
            V[i]  = I + B * Kx[i] + C * K2[i];
        }
        sT[0] = V[0] * v0 + V[1] * v1 + V[2] * v2;
        sT[1] = V[3] * v0 + V[4] * v1 + V[5] * v2;
        sT[2] = V[6] * v0 + V[7] * v1 + V[8] * v2;
    }
    if (tid < 9) sK[tid] = Kin[tid];
    __syncthreads();
    for (int i = tid; i < NV; i += 512) {
        float x = verts[3 * i + 0], y = verts[3 * i + 1], z = verts[3 * i + 2];
        float cx = sR[0] * x + sR[1] * y + sR[2] * z + sT[0];
        float cy = sR[3] * x + sR[4] * y + sR[5] * z + sT[1];
        float cz = sR[6] * x + sR[7] * y + sR[8] * z + sT[2];
        float u = sK[0] * cx + sK[1] * cy + sK[2] * cz;
        float v = sK[3] * cx + sK[4] * cy + sK[5] * cz;
        float w = sK[6] * cx + sK[7] * cy + sK[8] * cz;
        sxy[i] = make_float2((u / w) * 0.4f, (v / w) * 0.4f);
    }
    __syncthreads();
    int fbase = blockIdx.x * (NF / 4);
    for (int f = fbase + tid; f < fbase + NF / 4; f += 512) {
        int i0 = faces[3 * f + 0];
        int i1 = faces[3 * f + 1];
        int i2 = faces[3 * f + 2];
        float2 p0 = sxy[i0], p1 = sxy[i1], p2 = sxy[i2];
        float2 e[3];
        e[0] = make_float2(p1.x - p0.x, p1.y - p0.y);
        e[1] = make_float2(p2.x - p1.x, p2.y - p1.y);
        e[2] = make_float2(p0.x - p2.x, p0.y - p2.y);
        float2 a[3] = {p0, p1, p2};
        float area2 = e[0].y * e[2].x - e[0].x * e[2].y;
        float sgn = (area2 >= 0.f) ? 1.f : -1.f;
        float P[3], Q[3], Cc[3];
        #pragma unroll
        for (int k = 0; k < 3; k++) {
            float elen = sqrtf(e[k].x * e[k].x + e[k].y * e[k].y) + 1e-9f;
            float s = sgn / elen;
            float c0 = e[k].x * a[k].y - e[k].y * a[k].x;
            P[k]  = -s * e[k].y;
            Q[k]  =  s * e[k].x;
            Cc[k] = -s * c0;
            g_face[f * 3 + k] = make_float4(P[k], Q[k], Cc[k], 0.f);
        }
        // bbox of keep region {all d_k > THRESH}: triangle formed by pairwise
        // intersections of the shifted lines P x + Q y + (C - THRESH) = 0.
        float minx = 1e30f, maxx = -1e30f, miny = 1e30f, maxy = -1e30f;
        bool ok = true;
        #pragma unroll
        for (int k = 0; k < 3; k++) {
            int j = k, l = (k + 1) % 3;
            float det = P[j] * Q[l] - P[l] * Q[j];
            float rj = -(Cc[j] - THRESH);
            float rl = -(Cc[l] - THRESH);
            if (fabsf(det) < 1e-9f) { ok = false; }
            else {
                float inv = 1.f / det;
                float vx = (rj * Q[l] - rl * Q[j]) * inv;
                float vy = (P[j] * rl - P[l] * rj) * inv;
                if (!isfinite(vx) || !isfinite(vy)) ok = false;
                minx = fminf(minx, vx); maxx = fmaxf(maxx, vx);
                miny = fminf(miny, vy); maxy = fmaxf(maxy, vy);
            }
        }
        uchar4 bb;
        if (!ok) {
            bb = make_uchar4(0, 255, 0, 255);
        } else {
            int x0 = (int)floorf(minx - 1.f), x1 = (int)ceilf(maxx + 1.f);
            int y0 = (int)floorf(miny - 1.f), y1 = (int)ceilf(maxy + 1.f);
            bb.x = (unsigned char)min(max(x0, 0), 255);
            bb.y = (unsigned char)min(max(x1, 0), 255);
            bb.z = (unsigned char)min(max(y0, 0), 255);
            bb.w = (unsigned char)min(max(y1, 0), 255);
            // empty-on-screen bbox (x1<0 or x0>255) collapses to a point at
            // the clamp boundary -> at most one spurious keep column; safe.
            if (x1 < 0 || x0 > 255 || y1 < 0 || y0 > 255)
                bb = make_uchar4(1, 0, 1, 0);   // empty: x0 > x1 -> never kept
        }
        g_fbbox[f] = bb;
    }
}

// ---------------------------------------------------------------------------
// Kernel 2: super-tile cull (32x32 px) via bbox test, ordered compaction.
// ---------------------------------------------------------------------------
__global__ __launch_bounds__(512) void supercull_kernel() {
    __shared__ int swarp[16];
    __shared__ int scount;
    int tid  = threadIdx.x;
    int warp = tid >> 5, lane = tid & 31;
    int sx = blockIdx.x & 7, sy = blockIdx.x >> 3;
    int tx0 = sx * 32, ty0 = sy * 32;

    if (tid == 0) scount = 0;
    __syncthreads();

    for (int r = 0; r < NF / 512; r++) {
        int f = r * 512 + tid;
        uchar4 bb = g_fbbox[f];
        bool keep = ((int)bb.y >= tx0) && ((int)bb.x <= tx0 + 31) &&
                    ((int)bb.w >= ty0) && ((int)bb.z <= ty0 + 31);

        unsigned b = __ballot_sync(0xffffffffu, keep);
        if (lane == 0) swarp[warp] = __popc(b);
        __syncthreads();
        int base = scount;
        #pragma unroll
        for (int w = 0; w < 16; w++) base += (w < warp) ? swarp[w] : 0;
        if (keep)
            g_superlist[blockIdx.x][base + __popc(b & ((1u << lane) - 1u))] = (unsigned short)f;
        __syncthreads();
        if (tid == 0) {
            int tot = 0;
            #pragma unroll
            for (int w = 0; w < 16; w++) tot += swarp[w];
            scount += tot;
        }
        __syncthreads();
    }
    if (tid == 0) g_supercount[blockIdx.x] = scount;
}

// ---------------------------------------------------------------------------
// Kernel 3: rasterizer, 16x8 px tiles, 1024 CTAs x 512 threads.
// CTA = (tile, half). 16 warps = 16 face slices; each thread owns 4 pixels:
// column x, rows y, y+2, y+4, y+6. Cull via bbox (4B) test; only survivors
// load 48B face data. Branch-free inner loop; rcp flush every 8 faces.
// ---------------------------------------------------------------------------
__global__ __launch_bounds__(RT) void raster_kernel() {
    __shared__ float4 sfA[CHUNK], sfB[CHUNK], sfC[CHUNK];
    __shared__ float sprod[4][16][32];
    __shared__ int swarp[16];

    int tid  = threadIdx.x;
    int warp = tid >> 5, lane = tid & 31;
    int tix  = blockIdx.x & (NTILE - 1);
    int half = blockIdx.x >> 9;
    int bx = tix & 15, by = tix >> 4;          // 16 x 32 tiles of 16x8 px
    int stile = (by >> 2) * 8 + (bx >> 1);
    int supn = g_supercount[stile];

    float* prodout = g_prod + half * (RS * RS);

    int x  = bx * 16 + (lane & 15);
    int y0 = by * 8 + (lane >> 4);             // rows: y0, y0+2, y0+4, y0+6

    if (supn == 0) {                           // empty sky tile
        if (tid < 32) {
            int xx = bx * 16 + (tid & 15);
            int yy = by * 8 + (tid >> 4);
            #pragma unroll
            for (int r = 0; r < 4; r++)
                prodout[(yy + 2 * r) * RS + xx] = 1.f;
        }
        return;
    }

    int r0 = (supn * half) / NHALF;
    int r1 = (supn * (half + 1)) / NHALF;

    int tx0 = bx * 16, ty0 = by * 8;           // tile pixel range

    float px = (float)x + 0.5f;
    float py = (float)y0 + 0.5f;

    const unsigned short* sup = g_superlist[stile];
    float p0 = 1.f, p1 = 1.f, p2 = 1.f, p3 = 1.f;
    const float KEXP = 2.8853900817779268f;    // 2 * log2(e)

    for (int cbase = r0; cbase < r1; cbase += CHUNK) {
        int cn = min(CHUNK, r1 - cbase);

        // ---- cull this chunk via bbox (one face per thread) ----
        bool keep = false;
        int f = 0;
        if (tid < cn) {
            f = (int)sup[cbase + tid];
            uchar4 bb = g_fbbox[f];
            keep = ((int)bb.y >= tx0) && ((int)bb.x <= tx0 + 15) &&
                    ((int)bb.w >= ty0) && ((int)bb.z <= ty0 + 7);
        }
        unsigned b = __ballot_sync(0xffffffffu, keep);
        if (lane == 0) swarp[warp] = __popc(b);
        __syncthreads();
        int base = 0, nlist = 0;
        #pragma unroll
        for (int w = 0; w < 16; w++) {
            int c = swarp[w];
            base  += (w < warp) ? c : 0;
            nlist += c;
        }
        if (keep) {
            int pos = base + __popc(b & ((1u << lane) - 1u));
            sfA[pos] = g_face[f * 3 + 0];
            sfB[pos] = g_face[f * 3 + 1];
            sfC[pos] = g_face[f * 3 + 2];
        }
        __syncthreads();

        // ---- raster this chunk's compacted faces, slice = warp ----
        int s0 = (nlist * warp) >> 4;
        int s1 = (nlist * (warp + 1)) >> 4;
        float den0 = 1.f, den1 = 1.f, den2 = 1.f, den3 = 1.f;
        for (int i = s0; i < s1; i++) {
            float4 F0 = sfA[i], F1 = sfB[i], F2 = sfC[i];
            float a0 = fmaf(F0.y, py, fmaf(F0.x, px, F0.z));
            float a1 = fmaf(F1.y, py, fmaf(F1.x, px, F1.z));
            float a2 = fmaf(F2.y, py, fmaf(F2.x, px, F2.z));
            float q0 = F0.y + F0.y, q1 = F1.y + F1.y, q2 = F2.y + F2.y;
            float b0 = a0 + q0, b1 = a1 + q1, b2 = a2 + q2;
            float c0 = b0 + q0, c1 = b1 + q1, c2 = b2 + q2;
            float e0 = c0 + q0, e1 = c1 + q1, e2 = c2 + q2;
            float m0 = fminf(a0, fminf(a1, a2));
            float m1 = fminf(b0, fminf(b1, b2));
            float m2 = fminf(c0, fminf(c1, c2));
            float m3 = fminf(e0, fminf(e1, e2));
            float t0, t1, t2, t3;
            asm("ex2.approx.ftz.f32 %0, %1;" : "=f"(t0) : "f"(m0 * KEXP));
            asm("ex2.approx.ftz.f32 %0, %1;" : "=f"(t1) : "f"(m1 * KEXP));
            asm("ex2.approx.ftz.f32 %0, %1;" : "=f"(t2) : "f"(m2 * KEXP));
            asm("ex2.approx.ftz.f32 %0, %1;" : "=f"(t3) : "f"(m3 * KEXP));
            den0 *= (1.f + t0);
            den1 *= (1.f + t1);
            den2 *= (1.f + t2);
            den3 *= (1.f + t3);
            if (((i & 7) == 7) || (i == s1 - 1)) {   // flush batch
                float r0f, r1f, r2f, r3f;
                asm("rcp.approx.ftz.f32 %0, %1;" : "=f"(r0f) : "f"(den0));
                asm("rcp.approx.ftz.f32 %0, %1;" : "=f"(r1f) : "f"(den1));
                asm("rcp.approx.ftz.f32 %0, %1;" : "=f"(r2f) : "f"(den2));
                asm("rcp.approx.ftz.f32 %0, %1;" : "=f"(r3f) : "f"(den3));
                p0 *= r0f; p1 *= r1f; p2 *= r2f; p3 *= r3f;
                den0 = den1 = den2 = den3 = 1.f;
                if (__all_sync(0xffffffffu,
                               (p0 == 0.f) && (p1 == 0.f) && (p2 == 0.f) && (p3 == 0.f)))
                    break;
            }
        }

        // ---- CTA-wide absorbing-zero break ----
        bool wz = __all_sync(0xffffffffu,
                             (p0 == 0.f) && (p1 == 0.f) && (p2 == 0.f) && (p3 == 0.f));
        if (lane == 0) swarp[warp] = wz ? 1 : 0;
        __syncthreads();
        int alldead = 1;
        #pragma unroll
        for (int w = 0; w < 16; w++) alldead &= swarp[w];
        __syncthreads();   // protect swarp reuse next chunk
        if (alldead) break;
    }
    sprod[0][warp][lane] = p0;
    sprod[1][warp][lane] = p1;
    sprod[2][warp][lane] = p2;
    sprod[3][warp][lane] = p3;
    __syncthreads();

    // ---- combine 16 slice partials per pixel in ascending slice order ----
    if (tid < 32) {
        int xx = bx * 16 + (tid & 15);
        int yy = by * 8 + (tid >> 4);
        #pragma unroll
        for (int r = 0; r < 4; r++) {
            float p = sprod[r][0][tid];
            #pragma unroll
            for (int s = 1; s < 16; s++) p *= sprod[r][s][tid];
            prodout[(yy + 2 * r) * RS + xx] = p;
        }
    }
}

// ---------------------------------------------------------------------------
// Kernel 4: combine halves, upsample, crop, si, SSE; fused fixed-point loss
// (order-independent atomicAdd); last block writes out[0]. 4 px/thread.
// ---------------------------------------------------------------------------
__global__ __launch_bounds__(256) void finalize_kernel(const float* __restrict__ mask,
                                                       float* __restrict__ out,
                                                       int si_offset) {
    int idx = (blockIdx.x * 256 + threadIdx.x) * 4;
    int r = idx / IMGW;
    int c = idx - r * IMGW;
    int sr = (2 * r + 1) / 5;
    const float* prow0 = g_prod + sr * RS;
    const float* prow1 = g_prod + RS * RS + sr * RS;
    float4 m4 = *reinterpret_cast<const float4*>(mask + idx);
    float sq = 0.f;
    float si4[4];
    #pragma unroll
    for (int k = 0; k < 4; k++) {
        int sc = (2 * (c + k) + 1) / 5;
        float si = 1.f - prow0[sc] * prow1[sc];
        si4[k] = si;
        float d = si - ((const float*)&m4)[k];
        sq += d * d;
    }
    #pragma unroll
    for (int k = 0; k < 4; k++)
        out[idx + si_offset + k] = si4[k];

    if (!si_offset) return;   // no loss slot in output

    __shared__ float red[8];
    #pragma unroll
    for (int o = 16; o > 0; o >>= 1)
        sq += __shfl_down_sync(0xffffffffu, sq, o);
    int warp = threadIdx.x >> 5, lane = threadIdx.x & 31;
    if (lane == 0) red[warp] = sq;
    __syncthreads();
    if (threadIdx.x == 0) {
        float s = 0.f;
        #pragma unroll
        for (int w = 0; w < 8; w++) s += red[w];
        // fixed-point accumulate: block sum <= 1024, scale 2^32 -> fits u64
        unsigned long long fx = (unsigned long long)((double)s * 4294967296.0);
        atomicAdd(&g_loss_fx, fx);
        __threadfence();
        unsigned int done = atomicAdd(&g_done, 1u);
        if (done == FBLK - 1) {
            double total = (double)g_loss_fx * (1.0 / 4294967296.0);
            out[0] = (float)total;
        }
    }
}

// ---------------------------------------------------------------------------
extern "C" void kernel_launch(void* const* d_in, const int* in_sizes, int n_in,
                              void* d_out, int out_size) {
    const float* dof   = (const float*)d_in[0];
    const float* verts = (const float*)d_in[1];
    const int*   faces = (const int*)d_in[2];
    const float* K     = (const float*)d_in[3];
    const float* mask  = (const float*)d_in[4];
    float* out = (float*)d_out;

    int has_loss = (out_size >= NPIX + 1) ? 1 : 0;

    setup_face_kernel<<<4, 512>>>(dof, verts, K, faces);
    supercull_kernel<<<NSUPER, 512>>>();
    raster_kernel<<<NTILE * NHALF, RT>>>();
    finalize_kernel<<<FBLK, 256>>>(mask, out, has_loss);
}

// round 15
// speedup vs baseline: 1.7301x; 1.7301x over previous
#include <cuda_runtime.h>
#include <cstdint>

#define RS 256
#define NV 2048
#define NF 4096
#define IMGH 480
#define IMGW 640
#define NPIX (IMGH * IMGW)
#define FBLK (NPIX / 1024)   // finalize blocks (4 px/thread)
#define THRESH (-8.5f)       // exact: dmin < -8.5 -> factor == 1.0f bitwise
#define NSUPER 64            // 8x8 super-tiles of 32x32 px
#define RT 512               // raster CTA threads
#define CHUNK 512            // faces per cull/raster round
#define NHALF 2              // face-range splits per tile
#define NTILE 512            // 16x8-px tiles: 16 x 32

__device__ float4 g_face[NF * 3];
__device__ float  g_prod[NHALF * RS * RS];
__device__ unsigned long long g_loss_fx;
__device__ unsigned int g_done;
__device__ unsigned short g_superlist[NSUPER][NF];
__device__ int    g_supercount[NSUPER];
__device__ int    g_sorder[NSUPER];      // super-tiles sorted by count desc
__device__ unsigned int g_scdone;

// ---------------------------------------------------------------------------
// Kernel 1: fused se3_exp + vertex transform + projection + face coefficients
// ---------------------------------------------------------------------------
__global__ __launch_bounds__(512) void setup_face_kernel(
        const float* __restrict__ dof,
        const float* __restrict__ verts,
        const float* __restrict__ Kin,
        const int*   __restrict__ faces) {
    __shared__ float2 sxy[NV];
    __shared__ float sR[9], sT[3], sK[9];
    int tid = threadIdx.x;
    if (blockIdx.x == 0 && tid == 1) { g_loss_fx = 0ull; g_done = 0u; g_scdone = 0u; }
    if (tid == 0) {
        float v0 = dof[0], v1 = dof[1], v2 = dof[2];
        float w0 = dof[3], w1 = dof[4], w2 = dof[5];
        float th2 = w0 * w0 + w1 * w1 + w2 * w2;
        float th  = sqrtf(th2 + 1e-30f);
        bool small = th < 1e-4f;
        float th_s  = small ? 1.f : th;
        float th2_s = small ? 1.f : th2;
        float A = small ? (1.f - th2 / 6.f)   : (sinf(th_s) / th_s);
        float B = small ? (0.5f - th2 / 24.f) : ((1.f - cosf(th_s)) / th2_s);
        float C = small ? (1.f / 6.f - th2 / 120.f)
                        : ((th_s - sinf(th_s)) / (th2_s * th_s));
        float Kx[9] = {0.f, -w2,  w1,
                       w2,  0.f, -w0,
                      -w1,  w0,  0.f};
        float K2[9];
        #pragma unroll
        for (int r = 0; r < 3; r++)
            #pragma unroll
            for (int c = 0; c < 3; c++) {
                float acc = 0.f;
                #pragma unroll
                for (int k = 0; k < 3; k++) acc += Kx[r * 3 + k] * Kx[k * 3 + c];
                K2[r * 3 + c] = acc;
            }
        float V[9];
        #pragma unroll
        for (int i = 0; i < 9; i++) {
            float I = (i == 0 || i == 4 || i == 8) ? 1.f : 0.f;
            sR[i] = I + A * Kx[i] + B * K2[i];
            V[i]  = I + B * Kx[i] + C * K2[i];
        }
        sT[0] = V[0] * v0 + V[1] * v1 + V[2] * v2;
        sT[1] = V[3] * v0 + V[4] * v1 + V[5] * v2;
        sT[2] = V[6] * v0 + V[7] * v1 + V[8] * v2;
    }
    if (tid < 9) sK[tid] = Kin[tid];
    __syncthreads();
    for (int i = tid; i < NV; i += 512) {
        float x = verts[3 * i + 0], y = verts[3 * i + 1], z = verts[3 * i + 2];
        float cx = sR[0] * x + sR[1] * y + sR[2] * z + sT[0];
        float cy = sR[3] * x + sR[4] * y + sR[5] * z + sT[1];
        float cz = sR[6] * x + sR[7] * y + sR[8] * z + sT[2];
        float u = sK[0] * cx + sK[1] * cy + sK[2] * cz;
        float v = sK[3] * cx + sK[4] * cy + sK[5] * cz;
        float w = sK[6] * cx + sK[7] * cy + sK[8] * cz;
        sxy[i] = make_float2((u / w) * 0.4f, (v / w) * 0.4f);
    }
    __syncthreads();
    int fbase = blockIdx.x * (NF / 4);
    for (int f = fbase + tid; f < fbase + NF / 4; f += 512) {
        int i0 = faces[3 * f + 0];
        int i1 = faces[3 * f + 1];
        int i2 = faces[3 * f + 2];
        float2 p0 = sxy[i0], p1 = sxy[i1], p2 = sxy[i2];
        float2 e[3];
        e[0] = make_float2(p1.x - p0.x, p1.y - p0.y);
        e[1] = make_float2(p2.x - p1.x, p2.y - p1.y);
        e[2] = make_float2(p0.x - p2.x, p0.y - p2.y);
        float2 a[3] = {p0, p1, p2};
        float area2 = e[0].y * e[2].x - e[0].x * e[2].y;
        float sgn = (area2 >= 0.f) ? 1.f : -1.f;
        #pragma unroll
        for (int k = 0; k < 3; k++) {
            float elen = sqrtf(e[k].x * e[k].x + e[k].y * e[k].y) + 1e-9f;
            float s = sgn / elen;
            float c0 = e[k].x * a[k].y - e[k].y * a[k].x;
            g_face[f * 3 + k] = make_float4(-s * e[k].y, s * e[k].x, -s * c0, 0.f);
        }
    }
}

// ---------------------------------------------------------------------------
// Kernel 2: super-tile cull (32x32 px), ordered compaction, 512 threads.
// The LAST CTA (atomic counter) rank-sorts super-tiles by count descending
// into g_sorder (deterministic: ties broken by index).
// ---------------------------------------------------------------------------
__global__ __launch_bounds__(512) void supercull_kernel() {
    __shared__ int swarp[16];
    __shared__ int scount;
    __shared__ int slast;
    __shared__ int scnts[NSUPER];
    int tid  = threadIdx.x;
    int warp = tid >> 5, lane = tid & 31;
    int sx = blockIdx.x & 7, sy = blockIdx.x >> 3;
    float tcx = (float)(sx * 32 + 16);
    float tcy = (float)(sy * 32 + 16);

    if (tid == 0) scount = 0;
    __syncthreads();

    for (int r = 0; r < NF / 512; r++) {
        int f = r * 512 + tid;
        float4 E0 = g_face[f * 3 + 0];
        float4 E1 = g_face[f * 3 + 1];
        float4 E2 = g_face[f * 3 + 2];
        float m0 = fmaf(E0.x, tcx, fmaf(E0.y, tcy, E0.z)) + 15.5f * (fabsf(E0.x) + fabsf(E0.y));
        float m1 = fmaf(E1.x, tcx, fmaf(E1.y, tcy, E1.z)) + 15.5f * (fabsf(E1.x) + fabsf(E1.y));
        float m2 = fmaf(E2.x, tcx, fmaf(E2.y, tcy, E2.z)) + 15.5f * (fabsf(E2.x) + fabsf(E2.y));
        bool keep = (m0 >= THRESH) && (m1 >= THRESH) && (m2 >= THRESH);

        unsigned b = __ballot_sync(0xffffffffu, keep);
        if (lane == 0) swarp[warp] = __popc(b);
        __syncthreads();
        int base = scount;
        #pragma unroll
        for (int w = 0; w < 16; w++) base += (w < warp) ? swarp[w] : 0;
        if (keep)
            g_superlist[blockIdx.x][base + __popc(b & ((1u << lane) - 1u))] = (unsigned short)f;
        __syncthreads();
        if (tid == 0) {
            int tot = 0;
            #pragma unroll
            for (int w = 0; w < 16; w++) tot += swarp[w];
            scount += tot;
        }
        __syncthreads();
    }
    if (tid == 0) {
        g_supercount[blockIdx.x] = scount;
        __threadfence();
        unsigned int old = atomicAdd(&g_scdone, 1u);
        slast = (old == NSUPER - 1) ? 1 : 0;
    }
    __syncthreads();
    if (slast) {
        // last CTA: rank-sort 64 counts descending (deterministic)
        __threadfence();
        if (tid < NSUPER) scnts[tid] = g_supercount[tid];
        __syncthreads();
        if (tid < NSUPER) {
            int ci = scnts[tid];
            int rank = 0;
            #pragma unroll
            for (int j = 0; j < NSUPER; j++) {
                int cj = scnts[j];
                rank += (cj > ci || (cj == ci && j < tid)) ? 1 : 0;
            }
            g_sorder[rank] = tid;
        }
    }
}

// ---------------------------------------------------------------------------
// Kernel 3: rasterizer, 16x8 px tiles, 1024 CTAs x 512 threads.
// CTA bid -> (sorted super-tile, subtile, half): heaviest super-tiles launch
// first (wave-tail compression). 16 warps = 16 face slices; each thread owns
// 4 pixels: column x, rows y, y+2, y+4, y+6 (chained via d + 2Q).
// Branch-free inner loop; rcp flush every 8 faces; absorbing-zero breaks.
// ---------------------------------------------------------------------------
__global__ __launch_bounds__(RT) void raster_kernel() {
    __shared__ float4 sfA[CHUNK], sfB[CHUNK], sfC[CHUNK];
    __shared__ float sprod[4][16][32];
    __shared__ int swarp[16];

    int tid  = threadIdx.x;
    int warp = tid >> 5, lane = tid & 31;
    int sslot = blockIdx.x >> 4;               // 0..63 sorted super-tile slot
    int sub   = blockIdx.x & 15;
    int half  = sub >> 3;                      // 0..1
    int subt  = sub & 7;                       // 0..7 subtile within super
    int stile = g_sorder[sslot];
    int sx = stile & 7, sy = stile >> 3;
    int bx = sx * 2 + (subt & 1);              // tile coords: 16 x 32
    int by = sy * 4 + (subt >> 1);
    int supn = g_supercount[stile];

    float* prodout = g_prod + half * (RS * RS);

    int x  = bx * 16 + (lane & 15);
    int y0 = by * 8 + (lane >> 4);             // rows: y0, y0+2, y0+4, y0+6

    if (supn == 0) {                           // empty sky tile
        if (tid < 32) {
            int xx = bx * 16 + (tid & 15);
            int yy = by * 8 + (tid >> 4);
            #pragma unroll
            for (int r = 0; r < 4; r++)
                prodout[(yy + 2 * r) * RS + xx] = 1.f;
        }
        return;
    }

    int r0 = (supn * half) / NHALF;
    int r1 = (supn * (half + 1)) / NHALF;

    float tcx = (float)(bx * 16 + 8);
    float tcy = (float)(by * 8 + 4);

    float px = (float)x + 0.5f;
    float py = (float)y0 + 0.5f;

    const unsigned short* sup = g_superlist[stile];
    float p0 = 1.f, p1 = 1.f, p2 = 1.f, p3 = 1.f;
    const float KEXP = 2.8853900817779268f;    // 2 * log2(e)

    for (int cbase = r0; cbase < r1; cbase += CHUNK) {
        int cn = min(CHUNK, r1 - cbase);

        // ---- cull this chunk (one face per thread) ----
        bool keep = false;
        float4 E0, E1, E2;
        if (tid < cn) {
            int f = (int)sup[cbase + tid];
            E0 = g_face[f * 3 + 0];
            E1 = g_face[f * 3 + 1];
            E2 = g_face[f * 3 + 2];
            float m0 = fmaf(E0.x, tcx, fmaf(E0.y, tcy, E0.z)) + 7.5f * fabsf(E0.x) + 3.5f * fabsf(E0.y);
            float m1 = fmaf(E1.x, tcx, fmaf(E1.y, tcy, E1.z)) + 7.5f * fabsf(E1.x) + 3.5f * fabsf(E1.y);
            float m2 = fmaf(E2.x, tcx, fmaf(E2.y, tcy, E2.z)) + 7.5f * fabsf(E2.x) + 3.5f * fabsf(E2.y);
            keep = (m0 >= THRESH) && (m1 >= THRESH) && (m2 >= THRESH);
        }
        unsigned b = __ballot_sync(0xffffffffu, keep);
        if (lane == 0) swarp[warp] = __popc(b);
        __syncthreads();
        int base = 0, nlist = 0;
        #pragma unroll
        for (int w = 0; w < 16; w++) {
            int c = swarp[w];
            base  += (w < warp) ? c : 0;
            nlist += c;
        }
        if (keep) {
            int pos = base + __popc(b & ((1u << lane) - 1u));
            sfA[pos] = E0;
            sfB[pos] = E1;
            sfC[pos] = E2;
        }
        __syncthreads();

        // ---- raster this chunk's compacted faces, slice = warp ----
        int s0 = (nlist * warp) >> 4;
        int s1 = (nlist * (warp + 1)) >> 4;
        float den0 = 1.f, den1 = 1.f, den2 = 1.f, den3 = 1.f;
        for (int i = s0; i < s1; i++) {
            float4 F0 = sfA[i], F1 = sfB[i], F2 = sfC[i];
            float a0 = fmaf(F0.y, py, fmaf(F0.x, px, F0.z));
            float a1 = fmaf(F1.y, py, fmaf(F1.x, px, F1.z));
            float a2 = fmaf(F2.y, py, fmaf(F2.x, px, F2.z));
            float q0 = F0.y + F0.y, q1 = F1.y + F1.y, q2 = F2.y + F2.y;
            float b0 = a0 + q0, b1 = a1 + q1, b2 = a2 + q2;
            float c0 = b0 + q0, c1 = b1 + q1, c2 = b2 + q2;
            float e0 = c0 + q0, e1 = c1 + q1, e2 = c2 + q2;
            float m0 = fminf(a0, fminf(a1, a2));
            float m1 = fminf(b0, fminf(b1, b2));
            float m2 = fminf(c0, fminf(c1, c2));
            float m3 = fminf(e0, fminf(e1, e2));
            float t0, t1, t2, t3;
            asm("ex2.approx.ftz.f32 %0, %1;" : "=f"(t0) : "f"(m0 * KEXP));
            asm("ex2.approx.ftz.f32 %0, %1;" : "=f"(t1) : "f"(m1 * KEXP));
            asm("ex2.approx.ftz.f32 %0, %1;" : "=f"(t2) : "f"(m2 * KEXP));
            asm("ex2.approx.ftz.f32 %0, %1;" : "=f"(t3) : "f"(m3 * KEXP));
            den0 *= (1.f + t0);
            den1 *= (1.f + t1);
            den2 *= (1.f + t2);
            den3 *= (1.f + t3);
            if (((i & 7) == 7) || (i == s1 - 1)) {   // flush batch
                float r0f, r1f, r2f, r3f;
                asm("rcp.approx.ftz.f32 %0, %1;" : "=f"(r0f) : "f"(den0));
                asm("rcp.approx.ftz.f32 %0, %1;" : "=f"(r1f) : "f"(den1));
                asm("rcp.approx.ftz.f32 %0, %1;" : "=f"(r2f) : "f"(den2));
                asm("rcp.approx.ftz.f32 %0, %1;" : "=f"(r3f) : "f"(den3));
                p0 *= r0f; p1 *= r1f; p2 *= r2f; p3 *= r3f;
                den0 = den1 = den2 = den3 = 1.f;
                if (__all_sync(0xffffffffu,
                               (p0 == 0.f) && (p1 == 0.f) && (p2 == 0.f) && (p3 == 0.f)))
                    break;
            }
        }

        // ---- CTA-wide absorbing-zero break ----
        bool wz = __all_sync(0xffffffffu,
                             (p0 == 0.f) && (p1 == 0.f) && (p2 == 0.f) && (p3 == 0.f));
        if (lane == 0) swarp[warp] = wz ? 1 : 0;
        __syncthreads();
        int alldead = 1;
        #pragma unroll
        for (int w = 0; w < 16; w++) alldead &= swarp[w];
        __syncthreads();   // protect swarp reuse next chunk
        if (alldead) break;
    }
    sprod[0][warp][lane] = p0;
    sprod[1][warp][lane] = p1;
    sprod[2][warp][lane] = p2;
    sprod[3][warp][lane] = p3;
    __syncthreads();

    // ---- combine 16 slice partials per pixel in ascending slice order ----
    if (tid < 32) {
        int xx = bx * 16 + (tid & 15);
        int yy = by * 8 + (tid >> 4);
        #pragma unroll
        for (int r = 0; r < 4; r++) {
            float p = sprod[r][0][tid];
            #pragma unroll
            for (int s = 1; s < 16; s++) p *= sprod[r][s][tid];
            prodout[(yy + 2 * r) * RS + xx] = p;
        }
    }
}

// ---------------------------------------------------------------------------
// Kernel 4: combine halves, upsample, crop, si, SSE; fused fixed-point loss
// (order-independent atomicAdd); last block writes out[0]. 4 px/thread.
// ---------------------------------------------------------------------------
__global__ __launch_bounds__(256) void finalize_kernel(const float* __restrict__ mask,
                                                       float* __restrict__ out,
                                                       int si_offset) {
    int idx = (blockIdx.x * 256 + threadIdx.x) * 4;
    int r = idx / IMGW;
    int c = idx - r * IMGW;
    int sr = (2 * r + 1) / 5;
    const float* prow0 = g_prod + sr * RS;
    const float* prow1 = g_prod + RS * RS + sr * RS;
    float4 m4 = *reinterpret_cast<const float4*>(mask + idx);
    float sq = 0.f;
    float si4[4];
    #pragma unroll
    for (int k = 0; k < 4; k++) {
        int sc = (2 * (c + k) + 1) / 5;
        float si = 1.f - prow0[sc] * prow1[sc];
        si4[k] = si;
        float d = si - ((const float*)&m4)[k];
        sq += d * d;
    }
    #pragma unroll
    for (int k = 0; k < 4; k++)
        out[idx + si_offset + k] = si4[k];

    if (!si_offset) return;   // no loss slot in output

    __shared__ float red[8];
    #pragma unroll
    for (int o = 16; o > 0; o >>= 1)
        sq += __shfl_down_sync(0xffffffffu, sq, o);
    int warp = threadIdx.x >> 5, lane = threadIdx.x & 31;
    if (lane == 0) red[warp] = sq;
    __syncthreads();
    if (threadIdx.x == 0) {
        float s = 0.f;
        #pragma unroll
        for (int w = 0; w < 8; w++) s += red[w];
        // fixed-point accumulate: block sum <= 1024, scale 2^32 -> fits u64
        unsigned long long fx = (unsigned long long)((double)s * 4294967296.0);
        atomicAdd(&g_loss_fx, fx);
        __threadfence();
        unsigned int done = atomicAdd(&g_done, 1u);
        if (done == FBLK - 1) {
            double total = (double)g_loss_fx * (1.0 / 4294967296.0);
            out[0] = (float)total;
        }
    }
}

// ---------------------------------------------------------------------------
extern "C" void kernel_launch(void* const* d_in, const int* in_sizes, int n_in,
                              void* d_out, int out_size) {
    const float* dof   = (const float*)d_in[0];
    const float* verts = (const float*)d_in[1];
    const int*   faces = (const int*)d_in[2];
    const float* K     = (const float*)d_in[3];
    const float* mask  = (const float*)d_in[4];
    float* out = (float*)d_out;

    int has_loss = (out_size >= NPIX + 1) ? 1 : 0;

    setup_face_kernel<<<4, 512>>>(dof, verts, K, faces);
    supercull_kernel<<<NSUPER, 512>>>();
    raster_kernel<<<NTILE * NHALF, RT>>>();
    finalize_kernel<<<FBLK, 256>>>(mask, out, has_loss);
}